// round 9
// baseline (speedup 1.0000x reference)
#include <cuda_runtime.h>
#include <cuda_bf16.h>
#include <cstdint>

#define N_NODES 50000
#define N_EDGES 500000
#define EMB     128
#define HALF_N  25000
#define HALF_ELEMS 3200000u
#define INV_KEEP (1.0f/0.9f)
#define K1_GRID 296
#define NUM_TILES ((N_EDGES + 127) / 128)

__device__ float g_acc[(size_t)N_NODES * EMB];   // scatter accumulator
__device__ float g_hid[(size_t)N_NODES * EMB];   // H' = hidden @ Wm[0:128] + bm

typedef unsigned long long ull;

// ---------- packed f32x2 helpers ----------
__device__ __forceinline__ ull pack2(float lo, float hi) {
    ull r; asm("mov.b64 %0, {%1, %2};" : "=l"(r) : "f"(lo), "f"(hi)); return r;
}
__device__ __forceinline__ void unpack2(ull v, float& lo, float& hi) {
    asm("mov.b64 {%0, %1}, %2;" : "=f"(lo), "=f"(hi) : "l"(v));
}
__device__ __forceinline__ ull ffma2(ull a, ull b, ull c) {
    ull d; asm("fma.rn.f32x2 %0, %1, %2, %3;" : "=l"(d) : "l"(a), "l"(b), "l"(c));
    return d;
}
__device__ __forceinline__ void red_add_v4(float* addr, float4 v) {
    asm volatile("red.global.add.v4.f32 [%0], {%1, %2, %3, %4};"
                 :: "l"(addr), "f"(v.x), "f"(v.y), "f"(v.z), "f"(v.w) : "memory");
}

// ---------- JAX threefry2x32, key (0,42), partitionable ----------
__device__ __forceinline__ void tf2x32_42(unsigned c0, unsigned c1, unsigned& o0, unsigned& o1) {
    const unsigned k0 = 0u, k1 = 42u, k2 = 0x1BD11BDAu ^ 42u;
    unsigned x0 = c0 + k0, x1 = c1 + k1;
#define TF_R(r) { x0 += x1; x1 = __funnelshift_l(x1, x1, (r)); x1 ^= x0; }
#define TF_G0   TF_R(13) TF_R(15) TF_R(26) TF_R(6)
#define TF_G1   TF_R(17) TF_R(29) TF_R(16) TF_R(24)
    TF_G0; x0 += k1; x1 += k2 + 1u;
    TF_G1; x0 += k2; x1 += k0 + 2u;
    TF_G0; x0 += k0; x1 += k1 + 3u;
    TF_G1; x0 += k1; x1 += k2 + 4u;
    TF_G0; x0 += k2; x1 += k0 + 5u;
#undef TF_R
#undef TF_G0
#undef TF_G1
    o0 = x0; o1 = x1;
}
__device__ __forceinline__ float tf_uniform(unsigned b) {
    return __uint_as_float((b >> 9) | 0x3f800000u) - 1.0f;
}
__device__ __forceinline__ unsigned tf_bits_part(unsigned idx) {
    unsigned a, b; tf2x32_42(0u, idx, a, b); return a ^ b;
}

// ================= KP: H' = hidden @ Wm[0:128] + bm  (+ g_acc = boundary) =========
#define KP_SMEM ((128*128 + 128*128) * 4)

__global__ void __launch_bounds__(256, 1) kp_hid(
    const float* __restrict__ hidden, const float* __restrict__ Wm,
    const float* __restrict__ bm, const float* __restrict__ boundary)
{
    extern __shared__ float sm[];
    float* As = sm;              // [128k][128row]
    float* Bs = sm + 128 * 128;  // [128k][128col]

    const int t = threadIdx.x;
    const int base = blockIdx.x * 128;

    // fold of old k0: copy boundary -> g_acc for this tile's rows (overlaps staging)
#pragma unroll
    for (int i = 0; i < 16; ++i) {
        int g = blockIdx.x * 4096 + t + i * 256;
        if (g < N_NODES * EMB / 4)
            reinterpret_cast<float4*>(g_acc)[g] =
                reinterpret_cast<const float4*>(boundary)[g];
    }

    // Bs = Wm rows 0..127 — linear copy
#pragma unroll
    for (int i = 0; i < 16; ++i)
        ((float4*)Bs)[t + i * 256] = ((const float4*)Wm)[t + i * 256];

    // As: transpose-stage. thread: row lr = t&127, k-half = t>>7
    {
        int lr = t & 127;
        int gr = base + lr; if (gr >= N_NODES) gr = N_NODES - 1;
        const float* hrow = &hidden[(size_t)gr * EMB];
#pragma unroll
        for (int j = 0; j < 16; ++j) {
            int k0 = (t >> 7) * 64 + j * 4;
            float4 v = *(const float4*)&hrow[k0];
            As[(k0 + 0) * 128 + lr] = v.x;
            As[(k0 + 1) * 128 + lr] = v.y;
            As[(k0 + 2) * 128 + lr] = v.z;
            As[(k0 + 3) * 128 + lr] = v.w;
        }
    }
    __syncthreads();

    const int te = t >> 4, tc = t & 15;
    float4 b0 = *(const float4*)&bm[tc * 8];
    float4 b1 = *(const float4*)&bm[tc * 8 + 4];
    ull acc[4][8];
#pragma unroll
    for (int er = 0; er < 4; ++er) {
        acc[er][0] = pack2(b0.x, b0.x); acc[er][1] = pack2(b0.y, b0.y);
        acc[er][2] = pack2(b0.z, b0.z); acc[er][3] = pack2(b0.w, b0.w);
        acc[er][4] = pack2(b1.x, b1.x); acc[er][5] = pack2(b1.y, b1.y);
        acc[er][6] = pack2(b1.z, b1.z); acc[er][7] = pack2(b1.w, b1.w);
    }

#pragma unroll 4
    for (int k = 0; k < 128; ++k) {
        const ulonglong2* ap = (const ulonglong2*)&As[k * 128 + te * 8];
        ulonglong2 a01 = ap[0], a23 = ap[1];
        float4 q0 = *(const float4*)&Bs[k * 128 + tc * 8];
        float4 q1 = *(const float4*)&Bs[k * 128 + tc * 8 + 4];
        ull bp[8] = {pack2(q0.x, q0.x), pack2(q0.y, q0.y), pack2(q0.z, q0.z), pack2(q0.w, q0.w),
                     pack2(q1.x, q1.x), pack2(q1.y, q1.y), pack2(q1.z, q1.z), pack2(q1.w, q1.w)};
        ull a[4] = {a01.x, a01.y, a23.x, a23.y};
#pragma unroll
        for (int er = 0; er < 4; ++er)
#pragma unroll
            for (int c = 0; c < 8; ++c)
                acc[er][c] = ffma2(a[er], bp[c], acc[er][c]);
    }

#pragma unroll
    for (int er = 0; er < 4; ++er) {
        int r0 = base + te * 8 + er * 2;
        float lo[8], hi[8];
#pragma unroll
        for (int c = 0; c < 8; ++c) unpack2(acc[er][c], lo[c], hi[c]);
        if (r0 < N_NODES) {
            *(float4*)&g_hid[(size_t)r0 * EMB + tc * 8]     = make_float4(lo[0], lo[1], lo[2], lo[3]);
            *(float4*)&g_hid[(size_t)r0 * EMB + tc * 8 + 4] = make_float4(lo[4], lo[5], lo[6], lo[7]);
        }
        if (r0 + 1 < N_NODES) {
            *(float4*)&g_hid[(size_t)(r0 + 1) * EMB + tc * 8]     = make_float4(hi[0], hi[1], hi[2], hi[3]);
            *(float4*)&g_hid[(size_t)(r0 + 1) * EMB + tc * 8 + 4] = make_float4(hi[4], hi[5], hi[6], hi[7]);
        }
    }
}

// ================= K1: persistent pipelined edge GEMM + gather + relu + scatter ====
// Tile 128 edges x 128 cols, K=64. Double-buffered As + indices; Bs staged once.
// smem floats: As[2][64*128] (8192 each), Bs[64*128], src[2][128], dst[2][128]
#define K1A(b)   ((b) * 8192)
#define K1B      (2 * 8192)
#define K1SRC(b) (3 * 8192 + (b) * 256)
#define K1DST(b) (3 * 8192 + (b) * 256 + 128)
#define K1_SMEM  ((3 * 8192 + 512) * 4)

__global__ void __launch_bounds__(256, 2) k1_msg(
    const int* __restrict__ eidx, const float* __restrict__ eattr,
    const float* __restrict__ etime, const float* __restrict__ Wm)
{
    extern __shared__ float sm[];
    const int t = threadIdx.x;

    // Bs: Wm rows 128..191, staged ONCE per CTA
    {
        const float4* Wq = (const float4*)(Wm + 128 * EMB);
#pragma unroll
        for (int i = 0; i < 8; ++i)
            ((float4*)(sm + K1B))[t + i * 256] = Wq[t + i * 256];
    }

    const int se = t & 127, sel = t >> 7;     // staging map: edge, feature-half

    // ---- prologue: stage tile0 into buffer 0 ----
    int tile = blockIdx.x;
    {
        int ge = tile * 128 + se; if (ge >= N_EDGES) ge = N_EDGES - 1;
        const float* p = sel ? &etime[(size_t)ge * 32] : &eattr[(size_t)ge * 32];
        float* As = sm + K1A(0);
#pragma unroll
        for (int j = 0; j < 8; ++j) {
            float4 v = *(const float4*)&p[j * 4];
            int k0 = sel * 32 + j * 4;
            As[(k0 + 0) * 128 + se] = v.x;
            As[(k0 + 1) * 128 + se] = v.y;
            As[(k0 + 2) * 128 + se] = v.z;
            As[(k0 + 3) * 128 + se] = v.w;
        }
        int gi = tile * 128 + (t & 127); if (gi >= N_EDGES) gi = N_EDGES - 1;
        if (t < 128) sm[K1SRC(0) + t] = __int_as_float(eidx[gi]);
        else         sm[K1DST(0) + t - 128] = __int_as_float(eidx[N_EDGES + gi]);
    }

    const int te = t >> 4, tc = t & 15;
    int cur = 0;

    for (; tile < NUM_TILES; tile += K1_GRID, cur ^= 1) {
        __syncthreads();   // As[cur]/idx[cur] visible; prev epilogue done

        const float* As = sm + K1A(cur);
        const float* Bs = sm + K1B;

        // ---- mainloop: 128x128 tile, K=64 ----
        ull acc[4][8];
#pragma unroll
        for (int er = 0; er < 4; ++er)
#pragma unroll
            for (int c = 0; c < 8; ++c) acc[er][c] = 0ull;

#pragma unroll 4
        for (int k = 0; k < 64; ++k) {
            const ulonglong2* ap = (const ulonglong2*)&As[k * 128 + te * 8];
            ulonglong2 a01 = ap[0], a23 = ap[1];
            float4 q0 = *(const float4*)&Bs[k * 128 + tc * 8];
            float4 q1 = *(const float4*)&Bs[k * 128 + tc * 8 + 4];
            ull bp[8] = {pack2(q0.x, q0.x), pack2(q0.y, q0.y), pack2(q0.z, q0.z), pack2(q0.w, q0.w),
                         pack2(q1.x, q1.x), pack2(q1.y, q1.y), pack2(q1.z, q1.z), pack2(q1.w, q1.w)};
            ull a[4] = {a01.x, a01.y, a23.x, a23.y};
#pragma unroll
            for (int er = 0; er < 4; ++er)
#pragma unroll
                for (int c = 0; c < 8; ++c)
                    acc[er][c] = ffma2(a[er], bp[c], acc[er][c]);
        }

        // ---- issue staging LDGs for next tile (latency hides behind epilogue) ----
        const int ntile = tile + K1_GRID;
        const bool has_next = (ntile < NUM_TILES);
        float4 sv[8]; int si = 0, di = 0;
        if (has_next) {
            int ge = ntile * 128 + se; if (ge >= N_EDGES) ge = N_EDGES - 1;
            const float* p = sel ? &etime[(size_t)ge * 32] : &eattr[(size_t)ge * 32];
#pragma unroll
            for (int j = 0; j < 8; ++j) sv[j] = *(const float4*)&p[j * 4];
            int gi = ntile * 128 + (t & 127); if (gi >= N_EDGES) gi = N_EDGES - 1;
            si = eidx[gi]; di = eidx[N_EDGES + gi];
        }

        // ---- epilogue: msg = relu(H'[src] + acc); RED into g_acc[dst] ----
        const int* src_s = (const int*)(sm + K1SRC(cur));
        const int* dst_s = (const int*)(sm + K1DST(cur));
        const int ebase = tile * 128;
#pragma unroll
        for (int er = 0; er < 4; ++er) {
            int el = te * 8 + er * 2;
            // batch both halves' H' loads first (MLP)
            int s0 = src_s[el], s1 = src_s[el + 1];
            const float* hp0 = &g_hid[(size_t)s0 * EMB + tc * 8];
            const float* hp1 = &g_hid[(size_t)s1 * EMB + tc * 8];
            float4 h00 = *(const float4*)hp0, h01 = *(const float4*)(hp0 + 4);
            float4 h10 = *(const float4*)hp1, h11 = *(const float4*)(hp1 + 4);
            float lo[8], hi[8];
#pragma unroll
            for (int c = 0; c < 8; ++c) unpack2(acc[er][c], lo[c], hi[c]);
            if (ebase + el < N_EDGES) {
                int d = dst_s[el];
                float* base = &g_acc[(size_t)d * EMB + tc * 8];
                red_add_v4(base, make_float4(
                    fmaxf(lo[0] + h00.x, 0.f), fmaxf(lo[1] + h00.y, 0.f),
                    fmaxf(lo[2] + h00.z, 0.f), fmaxf(lo[3] + h00.w, 0.f)));
                red_add_v4(base + 4, make_float4(
                    fmaxf(lo[4] + h01.x, 0.f), fmaxf(lo[5] + h01.y, 0.f),
                    fmaxf(lo[6] + h01.z, 0.f), fmaxf(lo[7] + h01.w, 0.f)));
            }
            if (ebase + el + 1 < N_EDGES) {
                int d = dst_s[el + 1];
                float* base = &g_acc[(size_t)d * EMB + tc * 8];
                red_add_v4(base, make_float4(
                    fmaxf(hi[0] + h10.x, 0.f), fmaxf(hi[1] + h10.y, 0.f),
                    fmaxf(hi[2] + h10.z, 0.f), fmaxf(hi[3] + h10.w, 0.f)));
                red_add_v4(base + 4, make_float4(
                    fmaxf(hi[4] + h11.x, 0.f), fmaxf(hi[5] + h11.y, 0.f),
                    fmaxf(hi[6] + h11.z, 0.f), fmaxf(hi[7] + h11.w, 0.f)));
            }
        }

        // ---- STS staging into other buffer (data has arrived by now) ----
        if (has_next) {
            float* An = sm + K1A(cur ^ 1);
#pragma unroll
            for (int j = 0; j < 8; ++j) {
                int k0 = sel * 32 + j * 4;
                An[(k0 + 0) * 128 + se] = sv[j].x;
                An[(k0 + 1) * 128 + se] = sv[j].y;
                An[(k0 + 2) * 128 + se] = sv[j].z;
                An[(k0 + 3) * 128 + se] = sv[j].w;
            }
            if (t < 128) sm[K1SRC(cur ^ 1) + t] = __int_as_float(si);
            else         sm[K1DST(cur ^ 1) + t - 128] = __int_as_float(di);
        }
    }
}

// ================= K2: node GEMM + LN + relu + dropout (unchanged, passing) =========
#define K2_SMEM ((128*64 + 128*128) * 4)

__global__ void __launch_bounds__(256) k2_node(
    const float* __restrict__ Wl, const float* __restrict__ bl,
    const float* __restrict__ gamma, const float* __restrict__ beta,
    float* __restrict__ out)
{
    extern __shared__ float sm[];
    float* As = sm;              // [128][64] k-major
    float* Bs = sm + 128 * 64;   // [128][128]

    const int t  = threadIdx.x;
    const int tr = t >> 5, tc = t & 31;
    const int base = blockIdx.x * 32;

#pragma unroll
    for (int i = 0; i < 16; ++i) {
        int idx = t + i * 256;
        int r = idx >> 5, q = idx & 31;
        *(float4*)&Bs[r * EMB + q * 4] = *(const float4*)&Wl[r * EMB + q * 4];
    }
    {
        int lr = t & 63;
        int pr = base + (lr >> 1);
        int grow = ((pr < HALF_N) ? pr : (HALF_N - 1)) + ((lr & 1) ? HALF_N : 0);
#pragma unroll
        for (int j = 0; j < 8; ++j) {
            int q = (t >> 6) * 8 + j;
            float4 v = *(const float4*)&g_acc[(size_t)grow * EMB + q * 4];
            As[(q * 4 + 0) * 64 + lr] = v.x;
            As[(q * 4 + 1) * 64 + lr] = v.y;
            As[(q * 4 + 2) * 64 + lr] = v.z;
            As[(q * 4 + 3) * 64 + lr] = v.w;
        }
    }
    float4 blv = *(const float4*)&bl[tc * 4];
    ull acc[4][4];
#pragma unroll
    for (int p = 0; p < 4; ++p) {
        acc[p][0] = pack2(blv.x, blv.x); acc[p][1] = pack2(blv.y, blv.y);
        acc[p][2] = pack2(blv.z, blv.z); acc[p][3] = pack2(blv.w, blv.w);
    }
    __syncthreads();

#pragma unroll 8
    for (int k = 0; k < 128; ++k) {
        const ulonglong2* ap = (const ulonglong2*)&As[k * 64 + tr * 8];
        ulonglong2 a01 = ap[0], a23 = ap[1];
        float4 b = *(const float4*)&Bs[k * EMB + tc * 4];
        ull b0 = pack2(b.x, b.x), b1 = pack2(b.y, b.y);
        ull b2 = pack2(b.z, b.z), b3 = pack2(b.w, b.w);
        ull a[4] = {a01.x, a01.y, a23.x, a23.y};
#pragma unroll
        for (int p = 0; p < 4; ++p) {
            acc[p][0] = ffma2(a[p], b0, acc[p][0]);
            acc[p][1] = ffma2(a[p], b1, acc[p][1]);
            acc[p][2] = ffma2(a[p], b2, acc[p][2]);
            acc[p][3] = ffma2(a[p], b3, acc[p][3]);
        }
    }

    float4 gv = *(const float4*)&gamma[tc * 4];
    float4 bv = *(const float4*)&beta[tc * 4];
    float ga[4] = {gv.x, gv.y, gv.z, gv.w};
    float be[4] = {bv.x, bv.y, bv.z, bv.w};

#pragma unroll
    for (int p = 0; p < 4; ++p) {
        float lo[4], hi[4];
#pragma unroll
        for (int j = 0; j < 4; ++j) unpack2(acc[p][j], lo[j], hi[j]);

        float s0 = lo[0] + lo[1] + lo[2] + lo[3];
        float q0 = lo[0]*lo[0] + lo[1]*lo[1] + lo[2]*lo[2] + lo[3]*lo[3];
        float s1 = hi[0] + hi[1] + hi[2] + hi[3];
        float q1 = hi[0]*hi[0] + hi[1]*hi[1] + hi[2]*hi[2] + hi[3]*hi[3];
#pragma unroll
        for (int off = 16; off; off >>= 1) {
            s0 += __shfl_xor_sync(0xffffffffu, s0, off);
            q0 += __shfl_xor_sync(0xffffffffu, q0, off);
            s1 += __shfl_xor_sync(0xffffffffu, s1, off);
            q1 += __shfl_xor_sync(0xffffffffu, q1, off);
        }
        float m0 = s0 * (1.0f / EMB);
        float r0 = rsqrtf(q0 * (1.0f / EMB) - m0 * m0 + 1e-5f);
        float m1 = s1 * (1.0f / EMB);
        float r1 = rsqrtf(q1 * (1.0f / EMB) - m1 * m1 + 1e-5f);

        int rlow = base + tr * 4 + p;
        float o0[4], o1[4];
#pragma unroll
        for (int j = 0; j < 4; ++j) {
            float y0 = fmaxf((lo[j] - m0) * r0 * ga[j] + be[j], 0.f);
            float y1 = fmaxf((hi[j] - m1) * r1 * ga[j] + be[j], 0.f);
            unsigned idx0 = (unsigned)(rlow * EMB + tc * 4 + j);
            unsigned idx1 = idx0 + HALF_ELEMS;
            o0[j] = (tf_uniform(tf_bits_part(idx0)) < 0.9f) ? y0 * INV_KEEP : 0.f;
            o1[j] = (tf_uniform(tf_bits_part(idx1)) < 0.9f) ? y1 * INV_KEEP : 0.f;
        }
        if (rlow < HALF_N) {
            *(float4*)&out[(size_t)rlow * EMB + tc * 4] =
                make_float4(o0[0], o0[1], o0[2], o0[3]);
            *(float4*)&out[(size_t)(rlow + HALF_N) * EMB + tc * 4] =
                make_float4(o1[0], o1[1], o1[2], o1[3]);
        }
    }
}

// ================= launch ==================
extern "C" void kernel_launch(void* const* d_in, const int* in_sizes, int n_in,
                              void* d_out, int out_size) {
    (void)in_sizes; (void)n_in; (void)out_size;
    const float* hidden = (const float*)d_in[0];
    const int*   eidx   = (const int*)  d_in[1];
    const float* eattr  = (const float*)d_in[2];
    const float* etime  = (const float*)d_in[3];
    const float* bc     = (const float*)d_in[4];
    const float* Wm     = (const float*)d_in[5];
    const float* bm     = (const float*)d_in[6];
    const float* Wl     = (const float*)d_in[7];
    const float* bl     = (const float*)d_in[8];
    const float* gam    = (const float*)d_in[9];
    const float* bet    = (const float*)d_in[10];
    float* out = (float*)d_out;

    cudaFuncSetAttribute((const void*)kp_hid,
                         cudaFuncAttributeMaxDynamicSharedMemorySize, KP_SMEM);
    cudaFuncSetAttribute((const void*)k1_msg,
                         cudaFuncAttributeMaxDynamicSharedMemorySize, K1_SMEM);
    cudaFuncSetAttribute((const void*)k2_node,
                         cudaFuncAttributeMaxDynamicSharedMemorySize, K2_SMEM);

    kp_hid<<<(N_NODES + 127) / 128, 256, KP_SMEM>>>(hidden, Wm, bm, bc);
    k1_msg<<<K1_GRID, 256, K1_SMEM>>>(eidx, eattr, etime, Wm);
    k2_node<<<(HALF_N + 31) / 32, 256, K2_SMEM>>>(Wl, bl, gam, bet, out);
}

// round 11
// speedup vs baseline: 1.0011x; 1.0011x over previous
#include <cuda_runtime.h>
#include <cuda_bf16.h>
#include <cstdint>

#define N_NODES 50000
#define N_EDGES 500000
#define EMB     128
#define HALF_N  25000
#define HALF_ELEMS 3200000u
#define INV_KEEP (1.0f/0.9f)
#define NUM_TILES ((N_EDGES + 127) / 128)

__device__ float g_acc[(size_t)N_NODES * EMB];   // scatter accumulator
__device__ float g_hid[(size_t)N_NODES * EMB];   // H' = hidden @ Wm[0:128] + bm

typedef unsigned long long ull;

// ---------- packed f32x2 helpers ----------
__device__ __forceinline__ ull pack2(float lo, float hi) {
    ull r; asm("mov.b64 %0, {%1, %2};" : "=l"(r) : "f"(lo), "f"(hi)); return r;
}
__device__ __forceinline__ void unpack2(ull v, float& lo, float& hi) {
    asm("mov.b64 {%0, %1}, %2;" : "=f"(lo), "=f"(hi) : "l"(v));
}
__device__ __forceinline__ ull ffma2(ull a, ull b, ull c) {
    ull d; asm("fma.rn.f32x2 %0, %1, %2, %3;" : "=l"(d) : "l"(a), "l"(b), "l"(c));
    return d;
}
__device__ __forceinline__ void red_add_v4(float* addr, float4 v) {
    asm volatile("red.global.add.v4.f32 [%0], {%1, %2, %3, %4};"
                 :: "l"(addr), "f"(v.x), "f"(v.y), "f"(v.z), "f"(v.w) : "memory");
}

// ---------- JAX threefry2x32, key (0,42), partitionable ----------
__device__ __forceinline__ void tf2x32_42(unsigned c0, unsigned c1, unsigned& o0, unsigned& o1) {
    const unsigned k0 = 0u, k1 = 42u, k2 = 0x1BD11BDAu ^ 42u;
    unsigned x0 = c0 + k0, x1 = c1 + k1;
#define TF_R(r) { x0 += x1; x1 = __funnelshift_l(x1, x1, (r)); x1 ^= x0; }
#define TF_G0   TF_R(13) TF_R(15) TF_R(26) TF_R(6)
#define TF_G1   TF_R(17) TF_R(29) TF_R(16) TF_R(24)
    TF_G0; x0 += k1; x1 += k2 + 1u;
    TF_G1; x0 += k2; x1 += k0 + 2u;
    TF_G0; x0 += k0; x1 += k1 + 3u;
    TF_G1; x0 += k1; x1 += k2 + 4u;
    TF_G0; x0 += k2; x1 += k0 + 5u;
#undef TF_R
#undef TF_G0
#undef TF_G1
    o0 = x0; o1 = x1;
}
__device__ __forceinline__ float tf_uniform(unsigned b) {
    return __uint_as_float((b >> 9) | 0x3f800000u) - 1.0f;
}
__device__ __forceinline__ unsigned tf_bits_part(unsigned idx) {
    unsigned a, b; tf2x32_42(0u, idx, a, b); return a ^ b;
}

// ================= KP: H' = hidden @ Wm[0:128] + bm  (+ g_acc = boundary) =========
// 64-row tiles -> 96KB smem -> 2 CTAs/SM. thread (te=t>>4: rows te*4..+4,
// tc=t&15: cols tc*8..+8); acc[2][8] f32x2 pairs.
#define KP_SMEM ((128*64 + 128*128) * 4)

__global__ void __launch_bounds__(256, 2) kp_hid(
    const float* __restrict__ hidden, const float* __restrict__ Wm,
    const float* __restrict__ bm, const float* __restrict__ boundary)
{
    extern __shared__ float sm[];
    float* As = sm;              // [128k][64row]
    float* Bs = sm + 128 * 64;   // [128k][128col]

    const int t = threadIdx.x;
    const int base = blockIdx.x * 64;

    // fold of old k0: copy boundary -> g_acc (1.6M float4 over 782 blocks)
#pragma unroll
    for (int i = 0; i < 8; ++i) {
        int g = blockIdx.x * 2048 + t + i * 256;
        if (g < N_NODES * EMB / 4)
            reinterpret_cast<float4*>(g_acc)[g] =
                reinterpret_cast<const float4*>(boundary)[g];
    }

    // Bs = Wm rows 0..127 — linear copy (4096 float4)
#pragma unroll
    for (int i = 0; i < 16; ++i)
        ((float4*)Bs)[t + i * 256] = ((const float4*)Wm)[t + i * 256];

    // As: transpose-stage. thread: row lr = t&63, k-quarter = t>>6
    {
        int lr = t & 63;
        int gr = base + lr; if (gr >= N_NODES) gr = N_NODES - 1;
        const float* hrow = &hidden[(size_t)gr * EMB];
#pragma unroll
        for (int j = 0; j < 8; ++j) {
            int k0 = (t >> 6) * 32 + j * 4;
            float4 v = *(const float4*)&hrow[k0];
            As[(k0 + 0) * 64 + lr] = v.x;
            As[(k0 + 1) * 64 + lr] = v.y;
            As[(k0 + 2) * 64 + lr] = v.z;
            As[(k0 + 3) * 64 + lr] = v.w;
        }
    }
    __syncthreads();

    const int te = t >> 4, tc = t & 15;
    float4 b0 = *(const float4*)&bm[tc * 8];
    float4 b1 = *(const float4*)&bm[tc * 8 + 4];
    ull acc[2][8];
#pragma unroll
    for (int er = 0; er < 2; ++er) {
        acc[er][0] = pack2(b0.x, b0.x); acc[er][1] = pack2(b0.y, b0.y);
        acc[er][2] = pack2(b0.z, b0.z); acc[er][3] = pack2(b0.w, b0.w);
        acc[er][4] = pack2(b1.x, b1.x); acc[er][5] = pack2(b1.y, b1.y);
        acc[er][6] = pack2(b1.z, b1.z); acc[er][7] = pack2(b1.w, b1.w);
    }

#pragma unroll 4
    for (int k = 0; k < 128; ++k) {
        ulonglong2 a01 = *(const ulonglong2*)&As[k * 64 + te * 4];
        float4 q0 = *(const float4*)&Bs[k * 128 + tc * 8];
        float4 q1 = *(const float4*)&Bs[k * 128 + tc * 8 + 4];
        ull bp[8] = {pack2(q0.x, q0.x), pack2(q0.y, q0.y), pack2(q0.z, q0.z), pack2(q0.w, q0.w),
                     pack2(q1.x, q1.x), pack2(q1.y, q1.y), pack2(q1.z, q1.z), pack2(q1.w, q1.w)};
        ull a[2] = {a01.x, a01.y};
#pragma unroll
        for (int er = 0; er < 2; ++er)
#pragma unroll
            for (int c = 0; c < 8; ++c)
                acc[er][c] = ffma2(a[er], bp[c], acc[er][c]);
    }

#pragma unroll
    for (int er = 0; er < 2; ++er) {
        int r0 = base + te * 4 + er * 2;
        float lo[8], hi[8];
#pragma unroll
        for (int c = 0; c < 8; ++c) unpack2(acc[er][c], lo[c], hi[c]);
        if (r0 < N_NODES) {
            *(float4*)&g_hid[(size_t)r0 * EMB + tc * 8]     = make_float4(lo[0], lo[1], lo[2], lo[3]);
            *(float4*)&g_hid[(size_t)r0 * EMB + tc * 8 + 4] = make_float4(lo[4], lo[5], lo[6], lo[7]);
        }
        if (r0 + 1 < N_NODES) {
            *(float4*)&g_hid[(size_t)(r0 + 1) * EMB + tc * 8]     = make_float4(hi[0], hi[1], hi[2], hi[3]);
            *(float4*)&g_hid[(size_t)(r0 + 1) * EMB + tc * 8 + 4] = make_float4(hi[4], hi[5], hi[6], hi[7]);
        }
    }
}

// ================= K1: edge GEMM (E x 64 @ 64 x 128) + H' gather + relu + scatter ==
// R8 version (known good). Tile 128 edges x 128 cols, K=64; 2 CTAs/SM overlap.
#define K1_SMEM ((64*128 + 64*128) * 4 + 2*128*4)

__global__ void __launch_bounds__(256, 2) k1_msg(
    const int* __restrict__ eidx, const float* __restrict__ eattr,
    const float* __restrict__ etime, const float* __restrict__ Wm)
{
    extern __shared__ float sm[];
    float* As = sm;               // [64k][128edge]
    float* Bs = sm + 64 * 128;    // [64k][128col]
    int* src_s = (int*)(sm + 2 * 64 * 128);
    int* dst_s = src_s + 128;

    const int t = threadIdx.x;
    const int e0 = blockIdx.x * 128;

    // Bs = Wm rows 128..191 — linear copy (2048 float4)
    {
        const float4* Wq = (const float4*)(Wm + 128 * EMB);
#pragma unroll
        for (int i = 0; i < 8; ++i)
            ((float4*)Bs)[t + i * 256] = Wq[t + i * 256];
    }
    // edge indices
    if (t < 128) {
        int e = e0 + t;
        src_s[t] = (e < N_EDGES) ? eidx[e] : 0;
    } else {
        int e = e0 + t - 128;
        dst_s[t - 128] = (e < N_EDGES) ? eidx[N_EDGES + e] : -1;
    }
    // As: gather edge features, transpose. thread: edge e=t&127, sel=t>>7
    {
        int e = t & 127;
        int ge = e0 + e;
        int gec = (ge < N_EDGES) ? ge : (N_EDGES - 1);
        int sel = t >> 7;
        const float* ptr = sel ? &etime[(size_t)gec * 32] : &eattr[(size_t)gec * 32];
        int koff = sel * 32;
#pragma unroll
        for (int j = 0; j < 8; ++j) {
            float4 v = *(const float4*)&ptr[j * 4];
            As[(koff + j * 4 + 0) * 128 + e] = v.x;
            As[(koff + j * 4 + 1) * 128 + e] = v.y;
            As[(koff + j * 4 + 2) * 128 + e] = v.z;
            As[(koff + j * 4 + 3) * 128 + e] = v.w;
        }
    }
    __syncthreads();

    const int te = t >> 4, tc = t & 15;
    ull acc[4][8];
#pragma unroll
    for (int er = 0; er < 4; ++er)
#pragma unroll
        for (int c = 0; c < 8; ++c) acc[er][c] = 0ull;

#pragma unroll 4
    for (int k = 0; k < 64; ++k) {
        const ulonglong2* ap = (const ulonglong2*)&As[k * 128 + te * 8];
        ulonglong2 a01 = ap[0], a23 = ap[1];
        float4 q0 = *(const float4*)&Bs[k * 128 + tc * 8];
        float4 q1 = *(const float4*)&Bs[k * 128 + tc * 8 + 4];
        ull bp[8] = {pack2(q0.x, q0.x), pack2(q0.y, q0.y), pack2(q0.z, q0.z), pack2(q0.w, q0.w),
                     pack2(q1.x, q1.x), pack2(q1.y, q1.y), pack2(q1.z, q1.z), pack2(q1.w, q1.w)};
        ull a[4] = {a01.x, a01.y, a23.x, a23.y};
#pragma unroll
        for (int er = 0; er < 4; ++er)
#pragma unroll
            for (int c = 0; c < 8; ++c)
                acc[er][c] = ffma2(a[er], bp[c], acc[er][c]);
    }

    // epilogue: msg = relu(H'[src] + acc); scatter-add to g_acc[dst]
#pragma unroll
    for (int er = 0; er < 4; ++er) {
        float lo[8], hi[8];
#pragma unroll
        for (int c = 0; c < 8; ++c) unpack2(acc[er][c], lo[c], hi[c]);
        int el = te * 8 + er * 2;
#pragma unroll
        for (int half = 0; half < 2; ++half) {
            int e = el + half;
            float* v = half ? hi : lo;
            int sidx = src_s[e];
            int d = dst_s[e];
            const float* hp = &g_hid[(size_t)sidx * EMB + tc * 8];
            float4 h0 = *(const float4*)hp;
            float4 h1 = *(const float4*)(hp + 4);
            float4 o0 = make_float4(fmaxf(v[0] + h0.x, 0.f), fmaxf(v[1] + h0.y, 0.f),
                                    fmaxf(v[2] + h0.z, 0.f), fmaxf(v[3] + h0.w, 0.f));
            float4 o1 = make_float4(fmaxf(v[4] + h1.x, 0.f), fmaxf(v[5] + h1.y, 0.f),
                                    fmaxf(v[6] + h1.z, 0.f), fmaxf(v[7] + h1.w, 0.f));
            if (d >= 0) {
                float* base = &g_acc[(size_t)d * EMB + tc * 8];
                red_add_v4(base, o0);
                red_add_v4(base + 4, o1);
            }
        }
    }
}

// ================= K2: node GEMM + LN + relu + dropout ==================
#define K2_SMEM ((128*64 + 128*128) * 4)

__global__ void __launch_bounds__(256, 2) k2_node(
    const float* __restrict__ Wl, const float* __restrict__ bl,
    const float* __restrict__ gamma, const float* __restrict__ beta,
    float* __restrict__ out)
{
    extern __shared__ float sm[];
    float* As = sm;              // [128][64] k-major
    float* Bs = sm + 128 * 64;   // [128][128]

    const int t  = threadIdx.x;
    const int tr = t >> 5, tc = t & 31;
    const int base = blockIdx.x * 32;

#pragma unroll
    for (int i = 0; i < 16; ++i) {
        int idx = t + i * 256;
        int r = idx >> 5, q = idx & 31;
        *(float4*)&Bs[r * EMB + q * 4] = *(const float4*)&Wl[r * EMB + q * 4];
    }
    {
        int lr = t & 63;
        int pr = base + (lr >> 1);
        int grow = ((pr < HALF_N) ? pr : (HALF_N - 1)) + ((lr & 1) ? HALF_N : 0);
#pragma unroll
        for (int j = 0; j < 8; ++j) {
            int q = (t >> 6) * 8 + j;
            float4 v = *(const float4*)&g_acc[(size_t)grow * EMB + q * 4];
            As[(q * 4 + 0) * 64 + lr] = v.x;
            As[(q * 4 + 1) * 64 + lr] = v.y;
            As[(q * 4 + 2) * 64 + lr] = v.z;
            As[(q * 4 + 3) * 64 + lr] = v.w;
        }
    }
    float4 blv = *(const float4*)&bl[tc * 4];
    ull acc[4][4];
#pragma unroll
    for (int p = 0; p < 4; ++p) {
        acc[p][0] = pack2(blv.x, blv.x); acc[p][1] = pack2(blv.y, blv.y);
        acc[p][2] = pack2(blv.z, blv.z); acc[p][3] = pack2(blv.w, blv.w);
    }
    __syncthreads();

#pragma unroll 8
    for (int k = 0; k < 128; ++k) {
        const ulonglong2* ap = (const ulonglong2*)&As[k * 64 + tr * 8];
        ulonglong2 a01 = ap[0], a23 = ap[1];
        float4 b = *(const float4*)&Bs[k * EMB + tc * 4];
        ull b0 = pack2(b.x, b.x), b1 = pack2(b.y, b.y);
        ull b2 = pack2(b.z, b.z), b3 = pack2(b.w, b.w);
        ull a[4] = {a01.x, a01.y, a23.x, a23.y};
#pragma unroll
        for (int p = 0; p < 4; ++p) {
            acc[p][0] = ffma2(a[p], b0, acc[p][0]);
            acc[p][1] = ffma2(a[p], b1, acc[p][1]);
            acc[p][2] = ffma2(a[p], b2, acc[p][2]);
            acc[p][3] = ffma2(a[p], b3, acc[p][3]);
        }
    }

    float4 gv = *(const float4*)&gamma[tc * 4];
    float4 bv = *(const float4*)&beta[tc * 4];
    float ga[4] = {gv.x, gv.y, gv.z, gv.w};
    float be[4] = {bv.x, bv.y, bv.z, bv.w};

#pragma unroll
    for (int p = 0; p < 4; ++p) {
        float lo[4], hi[4];
#pragma unroll
        for (int j = 0; j < 4; ++j) unpack2(acc[p][j], lo[j], hi[j]);

        int rlow = base + tr * 4 + p;

        // batch the 8 independent threefry calls first (ARX chains interleave)
        unsigned bits0[4], bits1[4];
#pragma unroll
        for (int j = 0; j < 4; ++j) {
            unsigned idx0 = (unsigned)(rlow * EMB + tc * 4 + j);
            bits0[j] = tf_bits_part(idx0);
            bits1[j] = tf_bits_part(idx0 + HALF_ELEMS);
        }

        float s0 = lo[0] + lo[1] + lo[2] + lo[3];
        float q0 = lo[0]*lo[0] + lo[1]*lo[1] + lo[2]*lo[2] + lo[3]*lo[3];
        float s1 = hi[0] + hi[1] + hi[2] + hi[3];
        float q1 = hi[0]*hi[0] + hi[1]*hi[1] + hi[2]*hi[2] + hi[3]*hi[3];
#pragma unroll
        for (int off = 16; off; off >>= 1) {
            s0 += __shfl_xor_sync(0xffffffffu, s0, off);
            q0 += __shfl_xor_sync(0xffffffffu, q0, off);
            s1 += __shfl_xor_sync(0xffffffffu, s1, off);
            q1 += __shfl_xor_sync(0xffffffffu, q1, off);
        }
        float m0 = s0 * (1.0f / EMB);
        float r0 = rsqrtf(q0 * (1.0f / EMB) - m0 * m0 + 1e-5f);
        float m1 = s1 * (1.0f / EMB);
        float r1 = rsqrtf(q1 * (1.0f / EMB) - m1 * m1 + 1e-5f);

        float o0[4], o1[4];
#pragma unroll
        for (int j = 0; j < 4; ++j) {
            float y0 = fmaxf((lo[j] - m0) * r0 * ga[j] + be[j], 0.f);
            float y1 = fmaxf((hi[j] - m1) * r1 * ga[j] + be[j], 0.f);
            o0[j] = (tf_uniform(bits0[j]) < 0.9f) ? y0 * INV_KEEP : 0.f;
            o1[j] = (tf_uniform(bits1[j]) < 0.9f) ? y1 * INV_KEEP : 0.f;
        }
        if (rlow < HALF_N) {
            *(float4*)&out[(size_t)rlow * EMB + tc * 4] =
                make_float4(o0[0], o0[1], o0[2], o0[3]);
            *(float4*)&out[(size_t)(rlow + HALF_N) * EMB + tc * 4] =
                make_float4(o1[0], o1[1], o1[2], o1[3]);
        }
    }
}

// ================= launch ==================
extern "C" void kernel_launch(void* const* d_in, const int* in_sizes, int n_in,
                              void* d_out, int out_size) {
    (void)in_sizes; (void)n_in; (void)out_size;
    const float* hidden = (const float*)d_in[0];
    const int*   eidx   = (const int*)  d_in[1];
    const float* eattr  = (const float*)d_in[2];
    const float* etime  = (const float*)d_in[3];
    const float* bc     = (const float*)d_in[4];
    const float* Wm     = (const float*)d_in[5];
    const float* bm     = (const float*)d_in[6];
    const float* Wl     = (const float*)d_in[7];
    const float* bl     = (const float*)d_in[8];
    const float* gam    = (const float*)d_in[9];
    const float* bet    = (const float*)d_in[10];
    float* out = (float*)d_out;

    cudaFuncSetAttribute((const void*)kp_hid,
                         cudaFuncAttributeMaxDynamicSharedMemorySize, KP_SMEM);
    cudaFuncSetAttribute((const void*)k1_msg,
                         cudaFuncAttributeMaxDynamicSharedMemorySize, K1_SMEM);
    cudaFuncSetAttribute((const void*)k2_node,
                         cudaFuncAttributeMaxDynamicSharedMemorySize, K2_SMEM);

    kp_hid<<<(N_NODES + 63) / 64, 256, KP_SMEM>>>(hidden, Wm, bm, bc);
    k1_msg<<<NUM_TILES, 256, K1_SMEM>>>(eidx, eattr, etime, Wm);
    k2_node<<<(HALF_N + 31) / 32, 256, K2_SMEM>>>(Wl, bl, gam, bet, out);
}